// round 3
// baseline (speedup 1.0000x reference)
#include <cuda_runtime.h>
#include <cstdint>

// Problem constants (fixed by the reference)
#define NIN   1000
#define NH    3000
#define NOUT  10
#define NTOT  4010            // N = N_IN + N_H + N_OUT
#define LROW  3010            // L = N_H + N_OUT
#define COLS  16040           // N * A * B_FF  (matvec inner dim)
#define COLS4 4010            // COLS / 4
#define ROWS  6020            // L * A
#define TINYF 1.17549435e-38f

// Scratch (no allocations allowed)
__device__ __align__(16) float g_x[COLS];    // ff_tr flattened (n,a,b)
__device__ __align__(16) float g_fb[COLS];   // fb_tr flattened (n,a,b)
__device__ float g_pot[ROWS];                // ff potential (j,a) flat

// ---------------------------------------------------------------------------
// Kernel 1: temporal filtering.  x[n*4+a*2+b] = sum_t sh[n,a,T-1-t]*filt[b,t]
// ---------------------------------------------------------------------------
__global__ void prep_kernel(const float* __restrict__ sh,
                            const float* __restrict__ ffF,
                            const float* __restrict__ fbF) {
    int idx = blockIdx.x * blockDim.x + threadIdx.x;
    if (idx >= COLS) return;
    int n = idx >> 2;
    int a = (idx >> 1) & 1;
    int b = idx & 1;
    const float* s = sh + n * 20 + a * 10;
    float sff = 0.f, sfb = 0.f;
#pragma unroll
    for (int t = 0; t < 10; ++t) {
        float sp = s[9 - t];          // flipped history
        sff += sp * ffF[b * 10 + t];
        sfb += sp * fbF[b * 10 + t];
    }
    g_x[idx]  = sff;
    g_fb[idx] = sfb;
}

// ---------------------------------------------------------------------------
// Kernel 2: HBM-bound matvec (6020 x 16040) @ x.  4 rows per block so the
// x-vector is read from L2 once per block and reused in registers.
// ---------------------------------------------------------------------------
__global__ void __launch_bounds__(256) matvec_kernel(const float4* __restrict__ W) {
    int row0 = blockIdx.x * 4;
    const float4* w  = W + (size_t)row0 * COLS4;
    const float4* x4 = reinterpret_cast<const float4*>(g_x);

    float s0 = 0.f, s1 = 0.f, s2 = 0.f, s3 = 0.f;
    for (int c = threadIdx.x; c < COLS4; c += 256) {
        float4 xv = x4[c];
        float4 a = __ldg(w + c);
        float4 b = __ldg(w + COLS4 + c);
        float4 d = __ldg(w + 2 * COLS4 + c);
        float4 e = __ldg(w + 3 * COLS4 + c);
        s0 += a.x * xv.x + a.y * xv.y + a.z * xv.z + a.w * xv.w;
        s1 += b.x * xv.x + b.y * xv.y + b.z * xv.z + b.w * xv.w;
        s2 += d.x * xv.x + d.y * xv.y + d.z * xv.z + d.w * xv.w;
        s3 += e.x * xv.x + e.y * xv.y + e.z * xv.z + e.w * xv.w;
    }

#pragma unroll
    for (int o = 16; o > 0; o >>= 1) {
        s0 += __shfl_down_sync(0xffffffffu, s0, o);
        s1 += __shfl_down_sync(0xffffffffu, s1, o);
        s2 += __shfl_down_sync(0xffffffffu, s2, o);
        s3 += __shfl_down_sync(0xffffffffu, s3, o);
    }
    __shared__ float red[8][4];
    int lane = threadIdx.x & 31, wrp = threadIdx.x >> 5;
    if (lane == 0) {
        red[wrp][0] = s0; red[wrp][1] = s1; red[wrp][2] = s2; red[wrp][3] = s3;
    }
    __syncthreads();
    if (threadIdx.x < 4) {
        float s = 0.f;
#pragma unroll
        for (int k = 0; k < 8; ++k) s += red[k][threadIdx.x];
        g_pot[row0 + threadIdx.x] = s;
    }
}

// ---------------------------------------------------------------------------
// Kernel 3: fb potential + bias, JAX-exact Gumbel/categorical, log-softmax.
// PRNG: threefry2x32 with key(1) = (0,1), PARTITIONABLE layout (JAX >= 0.4.36
// default): bits[i] = H(hi=0, lo=i).x0 ^ H(hi=0, lo=i).x1
// ---------------------------------------------------------------------------
__device__ __forceinline__ void threefry01(uint32_t c0, uint32_t c1,
                                           uint32_t& o0, uint32_t& o1) {
    // key = (0, 1); ks2 = 0 ^ 1 ^ 0x1BD11BDA
    const uint32_t k0 = 0u, k1 = 1u, k2 = 0x1BD11BDBu;
    uint32_t x0 = c0 + k0, x1 = c1 + k1;
#define TF_RND(r) { x0 += x1; x1 = (x1 << (r)) | (x1 >> (32 - (r))); x1 ^= x0; }
    TF_RND(13) TF_RND(15) TF_RND(26) TF_RND(6)   x0 += k1; x1 += k2 + 1u;
    TF_RND(17) TF_RND(29) TF_RND(16) TF_RND(24)  x0 += k2; x1 += k0 + 2u;
    TF_RND(13) TF_RND(15) TF_RND(26) TF_RND(6)   x0 += k0; x1 += k1 + 3u;
    TF_RND(17) TF_RND(29) TF_RND(16) TF_RND(24)  x0 += k1; x1 += k2 + 4u;
    TF_RND(13) TF_RND(15) TF_RND(26) TF_RND(6)   x0 += k2; x1 += k0 + 5u;
#undef TF_RND
    o0 = x0; o1 = x1;
}

__device__ __forceinline__ float gumbel_at(int idx) {
    // Partitionable threefry: 64-bit counter i -> counts (i>>32, i&0xffffffff)
    // = (0, i) here; 32-bit output word = out0 ^ out1.
    uint32_t o0, o1;
    threefry01(0u, (uint32_t)idx, o0, o1);
    uint32_t bits = o0 ^ o1;
    float f = __uint_as_float((bits >> 9) | 0x3f800000u) - 1.0f;   // [0,1)
    float u = fmaxf(f + TINYF, TINYF);   // uniform(tiny, 1); (1-tiny)==1 in fp32
    return -logf(-logf(u));
}

__global__ void finalize_kernel(const float* __restrict__ inp,
                                const float* __restrict__ fbw,
                                const float* __restrict__ bias,
                                float* __restrict__ out) {
    int j = blockIdx.x * blockDim.x + threadIdx.x;
    if (j >= LROW) return;
    int n = NIN + j;
    float p0 = g_pot[2 * j]     + fbw[4 * j + 0] * g_fb[4 * n + 0]
                                + fbw[4 * j + 1] * g_fb[4 * n + 1] + bias[2 * j];
    float p1 = g_pot[2 * j + 1] + fbw[4 * j + 2] * g_fb[4 * n + 2]
                                + fbw[4 * j + 3] * g_fb[4 * n + 3] + bias[2 * j + 1];
    // TEMPERATURE == 1.0

    // log_softmax over logits (0, p0, p1)
    float m   = fmaxf(0.f, fmaxf(p0, p1));
    float lse = m + logf(expf(-m) + expf(p0 - m) + expf(p1 - m));
    float lp0 = -lse, lp1 = p0 - lse, lp2 = p1 - lse;

    float r;
    if (j < NH) {
        float v0 = gumbel_at(3 * j);
        float v1 = gumbel_at(3 * j + 1) + p0;
        float v2 = gumbel_at(3 * j + 2) + p1;
        int samp = 0; float best = v0;
        if (v1 > best) { best = v1; samp = 1; }   // first-wins argmax
        if (v2 > best) { samp = 2; }
        r = (samp == 0) ? lp0 : ((samp == 1) ? lp1 : lp2);
    } else {
        int i = j - NH;
        float s0 = inp[(NIN + i) * 2 + 0];
        float s1 = inp[(NIN + i) * 2 + 1];
        r = (1.f - s0 - s1) * lp0 + s0 * lp1 + s1 * lp2;
    }
    out[j] = r;
}

// ---------------------------------------------------------------------------
// Host: resolve inputs by element count (robust to metadata ordering).
// ---------------------------------------------------------------------------
extern "C" void kernel_launch(void* const* d_in, const int* in_sizes, int n_in,
                              void* d_out, int out_size) {
    const float* inp  = nullptr;
    const float* sh   = nullptr;
    const float* W    = nullptr;
    const float* fbw  = nullptr;
    const float* bias = nullptr;
    const float* ffF  = nullptr;
    const float* fbF  = nullptr;

    for (int i = 0; i < n_in; ++i) {
        const float* p = (const float*)d_in[i];
        switch (in_sizes[i]) {
            case 2020:     inp  = p; break;   // input_signal  (1010,2)
            case 80200:    sh   = p; break;   // spiking_history (4010,2,10)
            case 96560800: W    = p; break;   // ff_weights (3010,2,4010,2,2)
            case 12040:    fbw  = p; break;   // fb_weights (3010,2,2)
            case 6020:     bias = p; break;   // bias (3010,2)
            case 20:                          // ff_filter / fb_filter (identical)
                if (!ffF) ffF = p; else fbF = p;
                break;
            default: break;
        }
    }
    if (!fbF) fbF = ffF;
    float* out = (float*)d_out;

    prep_kernel<<<(COLS + 255) / 256, 256>>>(sh, ffF, fbF);
    matvec_kernel<<<ROWS / 4, 256>>>((const float4*)W);
    finalize_kernel<<<(LROW + 255) / 256, 256>>>(inp, fbw, bias, out);
}

// round 4
// speedup vs baseline: 1.0352x; 1.0352x over previous
#include <cuda_runtime.h>
#include <cstdint>

// Problem constants (fixed by the reference)
#define NIN   1000
#define NH    3000
#define NOUT  10
#define NTOT  4010            // N = N_IN + N_H + N_OUT
#define LROW  3010            // L = N_H + N_OUT
#define COLS  16040           // N * A * B_FF  (matvec inner dim)
#define COLS4 4010            // COLS / 4
#define ROWS  6020            // L * A
#define RPB   8               // rows per matvec block
#define TINYF 1.17549435e-38f

// Scratch (no allocations allowed)
__device__ __align__(16) float g_x[COLS];    // ff_tr flattened (n,a,b)
__device__ __align__(16) float g_fb[COLS];   // fb_tr flattened (n,a,b)
__device__ float g_pot[ROWS];                // ff potential (j,a) flat

// ---------------------------------------------------------------------------
// Kernel 1: temporal filtering. One thread per (n,a); computes both b values
// for ff and fb filters. x[n*4+a*2+b] = sum_t sh[n,a,9-t]*filt[b,t]
// ---------------------------------------------------------------------------
__global__ void prep_kernel(const float* __restrict__ sh,
                            const float* __restrict__ ffF,
                            const float* __restrict__ fbF) {
    int na = blockIdx.x * blockDim.x + threadIdx.x;   // 0 .. 8019
    if (na >= NTOT * 2) return;
    const float2* s2 = reinterpret_cast<const float2*>(sh + na * 10);
    float h[10];
#pragma unroll
    for (int i = 0; i < 5; ++i) {
        float2 v = s2[i];
        h[2 * i] = v.x; h[2 * i + 1] = v.y;
    }
    float ff0 = 0.f, ff1 = 0.f, fb0 = 0.f, fb1 = 0.f;
#pragma unroll
    for (int t = 0; t < 10; ++t) {
        float sp = h[9 - t];          // flipped history
        ff0 += sp * ffF[t];
        ff1 += sp * ffF[10 + t];
        fb0 += sp * fbF[t];
        fb1 += sp * fbF[10 + t];
    }
    reinterpret_cast<float2*>(g_x)[na]  = make_float2(ff0, ff1);
    reinterpret_cast<float2*>(g_fb)[na] = make_float2(fb0, fb1);
}

// ---------------------------------------------------------------------------
// Kernel 2: HBM-bound matvec (6020 x 16040) @ x.  8 rows per block: the
// x-vector is read from L2 once per block (48 MB total) and reused in
// registers; 8 independent LDG.128 in flight per thread per iteration.
// W is streamed with __ldcs (single-use, keep L2 for x / sh / pot).
// ---------------------------------------------------------------------------
__global__ void __launch_bounds__(256) matvec_kernel(const float4* __restrict__ W) {
    int row0 = blockIdx.x * RPB;
    const float4* x4 = reinterpret_cast<const float4*>(g_x);
    const float4* w  = W + (size_t)row0 * COLS4;

    float s[RPB];
#pragma unroll
    for (int r = 0; r < RPB; ++r) s[r] = 0.f;

    if (row0 + RPB <= ROWS) {
        for (int c = threadIdx.x; c < COLS4; c += 256) {
            float4 xv = x4[c];
            float4 a[RPB];
#pragma unroll
            for (int r = 0; r < RPB; ++r) a[r] = __ldcs(w + (size_t)r * COLS4 + c);
#pragma unroll
            for (int r = 0; r < RPB; ++r)
                s[r] += a[r].x * xv.x + a[r].y * xv.y + a[r].z * xv.z + a[r].w * xv.w;
        }
    } else {
        int nr = ROWS - row0;
        for (int c = threadIdx.x; c < COLS4; c += 256) {
            float4 xv = x4[c];
            for (int r = 0; r < nr; ++r) {
                float4 a = __ldcs(w + (size_t)r * COLS4 + c);
                s[r] += a.x * xv.x + a.y * xv.y + a.z * xv.z + a.w * xv.w;
            }
        }
    }

#pragma unroll
    for (int o = 16; o > 0; o >>= 1) {
#pragma unroll
        for (int r = 0; r < RPB; ++r)
            s[r] += __shfl_down_sync(0xffffffffu, s[r], o);
    }
    __shared__ float red[8][RPB];
    int lane = threadIdx.x & 31, wrp = threadIdx.x >> 5;
    if (lane == 0) {
#pragma unroll
        for (int r = 0; r < RPB; ++r) red[wrp][r] = s[r];
    }
    __syncthreads();
    if (threadIdx.x < RPB) {
        float sum = 0.f;
#pragma unroll
        for (int k = 0; k < 8; ++k) sum += red[k][threadIdx.x];
        int row = row0 + threadIdx.x;
        if (row < ROWS) g_pot[row] = sum;
    }
}

// ---------------------------------------------------------------------------
// Kernel 3: fb potential + bias, JAX-exact Gumbel/categorical, log-softmax.
// PRNG: threefry2x32 with key(1) = (0,1), partitionable layout:
// bits[i] = H(0, i).x0 ^ H(0, i).x1
// ---------------------------------------------------------------------------
__device__ __forceinline__ void threefry01(uint32_t c0, uint32_t c1,
                                           uint32_t& o0, uint32_t& o1) {
    const uint32_t k0 = 0u, k1 = 1u, k2 = 0x1BD11BDBu;
    uint32_t x0 = c0 + k0, x1 = c1 + k1;
#define TF_RND(r) { x0 += x1; x1 = (x1 << (r)) | (x1 >> (32 - (r))); x1 ^= x0; }
    TF_RND(13) TF_RND(15) TF_RND(26) TF_RND(6)   x0 += k1; x1 += k2 + 1u;
    TF_RND(17) TF_RND(29) TF_RND(16) TF_RND(24)  x0 += k2; x1 += k0 + 2u;
    TF_RND(13) TF_RND(15) TF_RND(26) TF_RND(6)   x0 += k0; x1 += k1 + 3u;
    TF_RND(17) TF_RND(29) TF_RND(16) TF_RND(24)  x0 += k1; x1 += k2 + 4u;
    TF_RND(13) TF_RND(15) TF_RND(26) TF_RND(6)   x0 += k2; x1 += k0 + 5u;
#undef TF_RND
    o0 = x0; o1 = x1;
}

__device__ __forceinline__ float gumbel_at(int idx) {
    uint32_t o0, o1;
    threefry01(0u, (uint32_t)idx, o0, o1);
    uint32_t bits = o0 ^ o1;
    float f = __uint_as_float((bits >> 9) | 0x3f800000u) - 1.0f;   // [0,1)
    float u = fmaxf(f + TINYF, TINYF);   // uniform(tiny,1); (1-tiny)==1 in fp32
    return -logf(-logf(u));
}

__global__ void finalize_kernel(const float* __restrict__ inp,
                                const float* __restrict__ fbw,
                                const float* __restrict__ bias,
                                float* __restrict__ out) {
    int j = blockIdx.x * blockDim.x + threadIdx.x;
    if (j >= LROW) return;
    int n = NIN + j;
    float p0 = g_pot[2 * j]     + fbw[4 * j + 0] * g_fb[4 * n + 0]
                                + fbw[4 * j + 1] * g_fb[4 * n + 1] + bias[2 * j];
    float p1 = g_pot[2 * j + 1] + fbw[4 * j + 2] * g_fb[4 * n + 2]
                                + fbw[4 * j + 3] * g_fb[4 * n + 3] + bias[2 * j + 1];
    // TEMPERATURE == 1.0

    // log_softmax over logits (0, p0, p1)
    float m   = fmaxf(0.f, fmaxf(p0, p1));
    float lse = m + logf(expf(-m) + expf(p0 - m) + expf(p1 - m));
    float lp0 = -lse, lp1 = p0 - lse, lp2 = p1 - lse;

    float r;
    if (j < NH) {
        float v0 = gumbel_at(3 * j);
        float v1 = gumbel_at(3 * j + 1) + p0;
        float v2 = gumbel_at(3 * j + 2) + p1;
        int samp = 0; float best = v0;
        if (v1 > best) { best = v1; samp = 1; }   // first-wins argmax
        if (v2 > best) { samp = 2; }
        r = (samp == 0) ? lp0 : ((samp == 1) ? lp1 : lp2);
    } else {
        int i = j - NH;
        float s0 = inp[(NIN + i) * 2 + 0];
        float s1 = inp[(NIN + i) * 2 + 1];
        r = (1.f - s0 - s1) * lp0 + s0 * lp1 + s1 * lp2;
    }
    out[j] = r;
}

// ---------------------------------------------------------------------------
// Host: resolve inputs by element count (robust to metadata ordering).
// ---------------------------------------------------------------------------
extern "C" void kernel_launch(void* const* d_in, const int* in_sizes, int n_in,
                              void* d_out, int out_size) {
    const float* inp  = nullptr;
    const float* sh   = nullptr;
    const float* W    = nullptr;
    const float* fbw  = nullptr;
    const float* bias = nullptr;
    const float* ffF  = nullptr;
    const float* fbF  = nullptr;

    for (int i = 0; i < n_in; ++i) {
        const float* p = (const float*)d_in[i];
        switch (in_sizes[i]) {
            case 2020:     inp  = p; break;   // input_signal  (1010,2)
            case 80200:    sh   = p; break;   // spiking_history (4010,2,10)
            case 96560800: W    = p; break;   // ff_weights (3010,2,4010,2,2)
            case 12040:    fbw  = p; break;   // fb_weights (3010,2,2)
            case 6020:     bias = p; break;   // bias (3010,2)
            case 20:                          // ff_filter / fb_filter (identical)
                if (!ffF) ffF = p; else fbF = p;
                break;
            default: break;
        }
    }
    if (!fbF) fbF = ffF;
    float* out = (float*)d_out;

    prep_kernel<<<(NTOT * 2 + 255) / 256, 256>>>(sh, ffF, fbF);
    matvec_kernel<<<(ROWS + RPB - 1) / RPB, 256>>>((const float4*)W);
    finalize_kernel<<<(LROW + 255) / 256, 256>>>(inp, fbw, bias, out);
}